// round 15
// baseline (speedup 1.0000x reference)
#include <cuda_runtime.h>
#include <cuda_bf16.h>
#include <stdint.h>
#include <math.h>

#define BB   64
#define TT_  1024
#define DDEC 1024
#define DENC 512
#define AA   512
#define NFF  32
#define KK   31
#define KPAD 576
#define NCH  18                 /* 32-col k-chunks */
#define ROWB 2304               /* bytes per packed row: 18 chunks x 128B (hi64|lo64) */
#define STAGE_BYTES 32768       /* A 16K + B 16K */
#define NSTG 3
#define SMEM_DYN (NSTG * STAGE_BYTES)
#define CTXCH 16                /* ctx t-chunks */

#define SW(o) ((o) ^ (((o) >> 3) & 0x70))

// ---------------- device scratch ----------------
__device__ char g_encs[(size_t)BB * TT_ * ROWB];   // packed A: [row][chunk][hi64|lo64]
__device__ char g_ws[(size_t)AA * ROWB];           // packed B: same layout
__device__ float g_locfeat[BB * TT_ * NFF];
__device__ float g_mel[BB * AA];
__device__ float g_energy4[4][BB * TT_];           // per-nq energy partials
__device__ float g_ctxp[CTXCH * BB * DENC];

// ---------------- helpers ----------------
__device__ __forceinline__ uint32_t smem_u32(const void* p) {
    uint32_t a;
    asm("{ .reg .u64 t; cvta.to.shared.u64 t, %1; cvt.u32.u64 %0, t; }" : "=r"(a) : "l"(p));
    return a;
}
__device__ __forceinline__ void cp16(uint32_t dst, const void* src) {
    asm volatile("cp.async.cg.shared.global [%0], [%1], 16;" :: "r"(dst), "l"(src));
}
#define CP_COMMIT() asm volatile("cp.async.commit_group;" ::: "memory")
#define CP_WAIT1()  asm volatile("cp.async.wait_group 1;" ::: "memory")
#define CP_WAIT0()  asm volatile("cp.async.wait_group 0;" ::: "memory")

__device__ __forceinline__ void ldmx4(uint32_t* r, uint32_t addr) {
    asm volatile("ldmatrix.sync.aligned.m8n8.x4.shared.b16 {%0,%1,%2,%3}, [%4];"
                 : "=r"(r[0]), "=r"(r[1]), "=r"(r[2]), "=r"(r[3]) : "r"(addr));
}
__device__ __forceinline__ void mma16816(float* d, const uint32_t* a, const uint32_t* b) {
    asm volatile("mma.sync.aligned.m16n8k16.row.col.f32.bf16.bf16.f32 "
                 "{%0,%1,%2,%3}, {%4,%5,%6,%7}, {%8,%9}, {%0,%1,%2,%3};"
                 : "+f"(d[0]), "+f"(d[1]), "+f"(d[2]), "+f"(d[3])
                 : "r"(a[0]), "r"(a[1]), "r"(a[2]), "r"(a[3]), "r"(b[0]), "r"(b[1]));
}
__device__ __forceinline__ void cvt_hilo(float x, unsigned short& hi, unsigned short& lo) {
    __nv_bfloat16 h = __float2bfloat16(x);
    float r = x - __bfloat162float(h);
    __nv_bfloat16 l = __float2bfloat16(r);
    hi = *reinterpret_cast<unsigned short*>(&h);
    lo = *reinterpret_cast<unsigned short*>(&l);
}
__device__ __forceinline__ float fast_tanh(float x) {
    x = fminf(fmaxf(x, -15.f), 15.f);
    float t = __expf(2.f * x);
    return __fdividef(t - 1.f, t + 1.f);
}

// ---------------- prep: pack fp32 -> bf16 hi/lo interleaved rows ----------------
__global__ void prep_enc_kernel(const float* __restrict__ enc) {
    int row = blockIdx.x;          // 0..65535 (b*T + t)
    int k4  = threadIdx.x;         // 0..143
    float4 v = make_float4(0.f, 0.f, 0.f, 0.f);
    if (k4 < 128)       v = *(const float4*)(enc + (size_t)row * DENC + k4 * 4);
    else if (k4 < 136)  v = *(const float4*)(g_locfeat + (size_t)row * NFF + (k4 - 128) * 4);
    unsigned short h0, l0, h1, l1, h2, l2, h3, l3;
    cvt_hilo(v.x, h0, l0); cvt_hilo(v.y, h1, l1);
    cvt_hilo(v.z, h2, l2); cvt_hilo(v.w, h3, l3);
    int k = k4 * 4, ch = k >> 5, ci = k & 31;
    char* base = g_encs + (size_t)row * ROWB + ch * 128;
    *(uint2*)(base + ci * 2)      = make_uint2((uint32_t)h0 | ((uint32_t)h1 << 16),
                                               (uint32_t)h2 | ((uint32_t)h3 << 16));
    *(uint2*)(base + 64 + ci * 2) = make_uint2((uint32_t)l0 | ((uint32_t)l1 << 16),
                                               (uint32_t)l2 | ((uint32_t)l3 << 16));
}

__global__ void prep_w_kernel(const float* __restrict__ w_enc,
                              const float* __restrict__ w_loc) {
    int a  = blockIdx.x;           // 0..511
    int k4 = threadIdx.x;          // 0..143
    float4 v = make_float4(0.f, 0.f, 0.f, 0.f);
    if (k4 < 128)       v = *(const float4*)(w_enc + (size_t)a * DENC + k4 * 4);
    else if (k4 < 136)  v = *(const float4*)(w_loc + (size_t)a * NFF + (k4 - 128) * 4);
    unsigned short h0, l0, h1, l1, h2, l2, h3, l3;
    cvt_hilo(v.x, h0, l0); cvt_hilo(v.y, h1, l1);
    cvt_hilo(v.z, h2, l2); cvt_hilo(v.w, h3, l3);
    int k = k4 * 4, ch = k >> 5, ci = k & 31;
    char* base = g_ws + (size_t)a * ROWB + ch * 128;
    *(uint2*)(base + ci * 2)      = make_uint2((uint32_t)h0 | ((uint32_t)h1 << 16),
                                               (uint32_t)h2 | ((uint32_t)h3 << 16));
    *(uint2*)(base + 64 + ci * 2) = make_uint2((uint32_t)l0 | ((uint32_t)l1 << 16),
                                               (uint32_t)l2 | ((uint32_t)l3 << 16));
}

// ---------------- mel projection ----------------
__global__ void melproj_kernel(const float* __restrict__ mel,
                               const float* __restrict__ w_in,
                               const float* __restrict__ b_in) {
    __shared__ float ms[DDEC];
    int b = blockIdx.x;
    int a = threadIdx.x;
    ms[a]       = mel[b * DDEC + a];
    ms[a + 512] = mel[b * DDEC + a + 512];
    __syncthreads();
    float acc = b_in[a];
    const float4* wr = (const float4*)(w_in + (size_t)a * DDEC);
#pragma unroll 8
    for (int e = 0; e < DDEC / 4; ++e) {
        float4 w = wr[e];
        float4 m = *(const float4*)&ms[e * 4];
        acc += w.x * m.x + w.y * m.y + w.z * m.z + w.w * m.w;
    }
    g_mel[b * AA + a] = acc;
}

// ---------------- conv1d(2->32, K=31, SAME) ----------------
__global__ void conv_kernel(const float* __restrict__ cum,
                            const float* __restrict__ conv_w) {
    __shared__ float ch[2][TT_ + 32];
    __shared__ float cw[NFF][2][KK + 1];
    int b = blockIdx.x;
    int tid = threadIdx.x;
    for (int i = tid; i < TT_ + 32; i += 256) {
        float v0 = 0.f, v1 = 0.f;
        int t = i - 15;
        if (t >= 0 && t < TT_) {
            v0 = cum[b * 2 * TT_ + t];
            v1 = cum[b * 2 * TT_ + TT_ + t];
        }
        ch[0][i] = v0; ch[1][i] = v1;
    }
    for (int i = tid; i < NFF * 2 * KK; i += 256) {
        int f = i / (2 * KK);
        int r = i % (2 * KK);
        cw[f][r / KK][r % KK] = conv_w[i];
    }
    __syncthreads();
    for (int idx = tid; idx < TT_ * NFF; idx += 256) {
        int t = idx >> 5;
        int f = idx & 31;
        float acc = 0.f;
#pragma unroll
        for (int k = 0; k < KK; ++k)
            acc += ch[0][t + k] * cw[f][0][k] + ch[1][t + k] * cw[f][1][k];
        g_locfeat[((size_t)b * TT_ + t) * NFF + f] = acc;
    }
}

// ---------------- HMMA energy GEMM: 128m x 128n per CTA, 256 thr, occ 2 --------
__global__ void __launch_bounds__(256, 2)
gemm_energy_kernel(const float* __restrict__ w_energy) {
    extern __shared__ char dsm[];
    __shared__ float mel_s[128];
    __shared__ float weng_s[128];
    __shared__ float red_s[8 * 64];

    uint32_t sdyn = smem_u32(dsm);
    int tid = threadIdx.x, w = tid >> 5, lane = tid & 31;
    int wm = w >> 2, wn = w & 3;           // warp grid 2m x 4n, warp tile 64x32
    int bx   = blockIdx.x;                 // tile*4 + nq (A L2-adjacency)
    int tile = bx >> 2, nq = bx & 3;
    int n0   = nq * 128;
    size_t brow0 = (size_t)tile * 128;
    int b = (int)(brow0 >> 10);

    if (tid < 128) {
        mel_s[tid]  = g_mel[b * AA + n0 + tid];
        weng_s[tid] = w_energy[n0 + tid];
    }

    float acc[4][4][4];
#pragma unroll
    for (int mt = 0; mt < 4; ++mt)
#pragma unroll
        for (int nt = 0; nt < 4; ++nt)
#pragma unroll
            for (int r = 0; r < 4; ++r) acc[mt][nt][r] = 0.f;

    // prologue: stage 0
    {
#pragma unroll
        for (int j = 0; j < 4; ++j) {
            int sg = tid + j * 256;
            int row = sg >> 3, s16 = sg & 7;
            uint32_t sw = SW((uint32_t)(row * 128 + s16 * 16));
            cp16(sdyn + sw,         g_encs + ((brow0 + row) * ROWB) + 0 * 128 + s16 * 16);
            cp16(sdyn + 16384 + sw, g_ws  + ((size_t)(n0 + row) * ROWB) + 0 * 128 + s16 * 16);
        }
        CP_COMMIT();
    }

#pragma unroll 3
    for (int kc = 0; kc < NCH; ++kc) {     // unroll 3: stage indices constant-fold
        if (kc < NCH - 1) {                // issue next stage at top (race-free mod 3)
            uint32_t sb = sdyn + ((kc + 1) % NSTG) * STAGE_BYTES;
#pragma unroll
            for (int j = 0; j < 4; ++j) {
                int sg = tid + j * 256;
                int row = sg >> 3, s16 = sg & 7;
                uint32_t sw = SW((uint32_t)(row * 128 + s16 * 16));
                cp16(sb + sw,         g_encs + ((brow0 + row) * ROWB) + (kc + 1) * 128 + s16 * 16);
                cp16(sb + 16384 + sw, g_ws  + ((size_t)(n0 + row) * ROWB) + (kc + 1) * 128 + s16 * 16);
            }
            CP_COMMIT();
            CP_WAIT1();                    // stage kc arrived (kc+1 may fly)
        } else {
            CP_WAIT0();
        }
        __syncthreads();

        uint32_t sa = sdyn + (kc % NSTG) * STAGE_BYTES;
#pragma unroll
        for (int ks = 0; ks < 2; ++ks) {
            // B: one x4 per nt: hi (lanes 0-15, +0) | lo (lanes 16-31, +64)
            uint32_t bf[4][4];
#pragma unroll
            for (int nt = 0; nt < 4; ++nt) {
                int brow = wn * 32 + nt * 8 + (lane & 7);
                uint32_t off = brow * 128 + ((lane & 16) ? 64u : 0u)
                             + ks * 32 + ((lane >> 3) & 1) * 16;
                ldmx4(bf[nt], sa + 16384 + SW(off));
            }
#pragma unroll
            for (int mt = 0; mt < 4; ++mt) {
                int arow = wm * 64 + mt * 16 + (lane & 15);
                uint32_t abase = arow * 128 + ks * 32 + ((lane >> 4) & 1) * 16;
                uint32_t ah[4], al[4];
                ldmx4(ah, sa + SW(abase));
                ldmx4(al, sa + SW(abase + 64));
#pragma unroll
                for (int nt = 0; nt < 4; ++nt) {
                    mma16816(acc[mt][nt], ah, &bf[nt][0]);
                    mma16816(acc[mt][nt], ah, &bf[nt][2]);
                    mma16816(acc[mt][nt], al, &bf[nt][0]);
                }
            }
        }
    }

    // ---- epilogue: tanh(+mel)*weng, reduce over this CTA's 128 cols ----
#pragma unroll
    for (int mt = 0; mt < 4; ++mt) {
        float s0 = 0.f, s1 = 0.f;
#pragma unroll
        for (int nt = 0; nt < 4; ++nt) {
            int n = wn * 32 + nt * 8 + (lane & 3) * 2;   // local col in [0,128)
            s0 += fast_tanh(acc[mt][nt][0] + mel_s[n]) * weng_s[n]
                + fast_tanh(acc[mt][nt][1] + mel_s[n + 1]) * weng_s[n + 1];
            s1 += fast_tanh(acc[mt][nt][2] + mel_s[n]) * weng_s[n]
                + fast_tanh(acc[mt][nt][3] + mel_s[n + 1]) * weng_s[n + 1];
        }
        s0 += __shfl_xor_sync(0xffffffffu, s0, 1);
        s0 += __shfl_xor_sync(0xffffffffu, s0, 2);
        s1 += __shfl_xor_sync(0xffffffffu, s1, 1);
        s1 += __shfl_xor_sync(0xffffffffu, s1, 2);
        if ((lane & 3) == 0) {
            red_s[w * 64 + mt * 16 + (lane >> 2)]     = s0;
            red_s[w * 64 + mt * 16 + 8 + (lane >> 2)] = s1;
        }
    }
    __syncthreads();
    if (tid < 128) {
        int rwm = tid >> 6, rr = tid & 63;
        float e = 0.f;
#pragma unroll
        for (int wn2 = 0; wn2 < 4; ++wn2)
            e += red_s[(rwm * 4 + wn2) * 64 + rr];
        g_energy4[nq][brow0 + tid] = e;    // disjoint per-nq partials: no atomics
    }
}

// ---------------- softmax (sums 4 partials, applies mask), writes weights ------
__global__ void softmax_kernel(const int* __restrict__ mask, float* __restrict__ out) {
    __shared__ float red[256];
    int b = blockIdx.x, tid = threadIdx.x;
    const int* mk = mask + b * TT_;
    float x[4];
    float m = -INFINITY;
#pragma unroll
    for (int j = 0; j < 4; ++j) {
        int t = b * TT_ + tid + j * 256;
        float e = g_energy4[0][t] + g_energy4[1][t] + g_energy4[2][t] + g_energy4[3][t];
        x[j] = (mk[tid + j * 256] != 0) ? -INFINITY : e;
        m = fmaxf(m, x[j]);
    }
    red[tid] = m; __syncthreads();
    for (int s = 128; s > 0; s >>= 1) {
        if (tid < s) red[tid] = fmaxf(red[tid], red[tid + s]);
        __syncthreads();
    }
    m = red[0]; __syncthreads();
    float sum = 0.f;
#pragma unroll
    for (int j = 0; j < 4; ++j) { x[j] = expf(x[j] - m); sum += x[j]; }
    red[tid] = sum; __syncthreads();
    for (int s = 128; s > 0; s >>= 1) {
        if (tid < s) red[tid] += red[tid + s];
        __syncthreads();
    }
    float inv = 1.0f / red[0];
    float* wout = out + BB * DENC + b * TT_;
#pragma unroll
    for (int j = 0; j < 4; ++j) wout[tid + j * 256] = x[j] * inv;
}

// ---------------- context: split over 16 t-chunks (1024 CTAs), then reduce ------
__global__ void ctx_part_kernel(const float* __restrict__ enc,
                                const float* __restrict__ out) {
    __shared__ float ws[64];
    int b = blockIdx.y, ck = blockIdx.x, tid = threadIdx.x;
    int t0 = ck * 64;
    if (tid < 64) ws[tid] = out[BB * DENC + b * TT_ + t0 + tid];
    __syncthreads();
    int e = tid * 2;
    float2 acc = make_float2(0.f, 0.f);
    const float* ep = enc + ((size_t)b * TT_ + t0) * DENC + e;
#pragma unroll 8
    for (int t = 0; t < 64; ++t) {
        float2 v = *(const float2*)(ep + (size_t)t * DENC);
        acc.x += ws[t] * v.x;
        acc.y += ws[t] * v.y;
    }
    *(float2*)&g_ctxp[((size_t)ck * BB + b) * DENC + e] = acc;
}

__global__ void ctx_reduce_kernel(float* __restrict__ out) {
    int b = blockIdx.x, e = threadIdx.x;
    float s = 0.f;
#pragma unroll
    for (int c = 0; c < CTXCH; ++c) s += g_ctxp[((size_t)c * BB + b) * DENC + e];
    out[b * DENC + e] = s;
}

// ---------------- launch ----------------
extern "C" void kernel_launch(void* const* d_in, const int* in_sizes, int n_in,
                              void* d_out, int out_size) {
    const float* mel      = (const float*)d_in[0];
    const float* enc      = (const float*)d_in[1];
    const float* cum      = (const float*)d_in[2];
    const int*   mask     = (const int*)d_in[3];
    const float* w_in     = (const float*)d_in[4];
    const float* b_in     = (const float*)d_in[5];
    const float* w_enc    = (const float*)d_in[6];
    const float* conv_w   = (const float*)d_in[7];
    const float* w_loc    = (const float*)d_in[8];
    const float* w_energy = (const float*)d_in[9];
    float* out = (float*)d_out;

    cudaFuncSetAttribute(gemm_energy_kernel,
                         cudaFuncAttributeMaxDynamicSharedMemorySize, SMEM_DYN);

    conv_kernel<<<BB, 256>>>(cum, conv_w);
    melproj_kernel<<<BB, 512>>>(mel, w_in, b_in);
    prep_w_kernel<<<AA, 144>>>(w_enc, w_loc);
    prep_enc_kernel<<<BB * TT_, 144>>>(enc);
    gemm_energy_kernel<<<2048, 256, SMEM_DYN>>>(w_energy);
    softmax_kernel<<<BB, 256>>>(mask, out);
    dim3 gc(CTXCH, BB);
    ctx_part_kernel<<<gc, 256>>>(enc, out);
    ctx_reduce_kernel<<<BB, 512>>>(out);
}

// round 16
// speedup vs baseline: 1.1372x; 1.1372x over previous
#include <cuda_runtime.h>
#include <cuda_bf16.h>
#include <stdint.h>
#include <math.h>

#define BB   64
#define TT_  1024
#define DDEC 1024
#define DENC 512
#define AA   512
#define NFF  32
#define KK   31
#define KPAD 576
#define NCH  18                 /* 32-col k-chunks */
#define ROWB 2304               /* bytes per packed row: 18 chunks x 128B (hi64|lo64) */
#define STAGE_BYTES 32768       /* A 16K + B 16K */
#define NSTG 3
#define SMEM_DYN (NSTG * STAGE_BYTES)

#define SW(o) ((o) ^ (((o) >> 3) & 0x70))

// ---------------- device scratch ----------------
__device__ char g_encs[(size_t)BB * TT_ * ROWB];   // packed A: [row][chunk][hi64|lo64]
__device__ char g_ws[(size_t)AA * ROWB];           // packed B: same layout
__device__ float g_locfeat[BB * TT_ * NFF];
__device__ float g_mel[BB * AA];
__device__ float g_energy4[4][BB * TT_];           // per-nq energy partials
__device__ float g_ctxp[8 * BB * DENC];

// ---------------- helpers ----------------
__device__ __forceinline__ uint32_t smem_u32(const void* p) {
    uint32_t a;
    asm("{ .reg .u64 t; cvta.to.shared.u64 t, %1; cvt.u32.u64 %0, t; }" : "=r"(a) : "l"(p));
    return a;
}
__device__ __forceinline__ void cp16(uint32_t dst, const void* src) {
    asm volatile("cp.async.cg.shared.global [%0], [%1], 16;" :: "r"(dst), "l"(src));
}
#define CP_COMMIT() asm volatile("cp.async.commit_group;" ::: "memory")
#define CP_WAIT1()  asm volatile("cp.async.wait_group 1;" ::: "memory")
#define CP_WAIT0()  asm volatile("cp.async.wait_group 0;" ::: "memory")

__device__ __forceinline__ void ldmx4(uint32_t* r, uint32_t addr) {
    asm volatile("ldmatrix.sync.aligned.m8n8.x4.shared.b16 {%0,%1,%2,%3}, [%4];"
                 : "=r"(r[0]), "=r"(r[1]), "=r"(r[2]), "=r"(r[3]) : "r"(addr));
}
__device__ __forceinline__ void mma16816(float* d, const uint32_t* a, const uint32_t* b) {
    asm volatile("mma.sync.aligned.m16n8k16.row.col.f32.bf16.bf16.f32 "
                 "{%0,%1,%2,%3}, {%4,%5,%6,%7}, {%8,%9}, {%0,%1,%2,%3};"
                 : "+f"(d[0]), "+f"(d[1]), "+f"(d[2]), "+f"(d[3])
                 : "r"(a[0]), "r"(a[1]), "r"(a[2]), "r"(a[3]), "r"(b[0]), "r"(b[1]));
}
__device__ __forceinline__ void cvt_hilo(float x, unsigned short& hi, unsigned short& lo) {
    __nv_bfloat16 h = __float2bfloat16(x);
    float r = x - __bfloat162float(h);
    __nv_bfloat16 l = __float2bfloat16(r);
    hi = *reinterpret_cast<unsigned short*>(&h);
    lo = *reinterpret_cast<unsigned short*>(&l);
}
__device__ __forceinline__ float fast_tanh(float x) {
    x = fminf(fmaxf(x, -15.f), 15.f);
    float t = __expf(2.f * x);
    return __fdividef(t - 1.f, t + 1.f);
}

// ---------------- prep: pack fp32 -> bf16 hi/lo interleaved rows ----------------
// 2 rows per block, 288 threads = 9 full warps (no half-warp waste)
__global__ void prep_enc_kernel(const float* __restrict__ enc) {
    int tid = threadIdx.x;                 // 0..287
    int r   = tid / 144;                   // 0..1
    int k4  = tid - r * 144;               // 0..143
    int row = blockIdx.x * 2 + r;          // 0..65535
    float4 v = make_float4(0.f, 0.f, 0.f, 0.f);
    if (k4 < 128)       v = *(const float4*)(enc + (size_t)row * DENC + k4 * 4);
    else if (k4 < 136)  v = *(const float4*)(g_locfeat + (size_t)row * NFF + (k4 - 128) * 4);
    unsigned short h0, l0, h1, l1, h2, l2, h3, l3;
    cvt_hilo(v.x, h0, l0); cvt_hilo(v.y, h1, l1);
    cvt_hilo(v.z, h2, l2); cvt_hilo(v.w, h3, l3);
    int k = k4 * 4, ch = k >> 5, ci = k & 31;
    char* base = g_encs + (size_t)row * ROWB + ch * 128;
    *(uint2*)(base + ci * 2)      = make_uint2((uint32_t)h0 | ((uint32_t)h1 << 16),
                                               (uint32_t)h2 | ((uint32_t)h3 << 16));
    *(uint2*)(base + 64 + ci * 2) = make_uint2((uint32_t)l0 | ((uint32_t)l1 << 16),
                                               (uint32_t)l2 | ((uint32_t)l3 << 16));
}

__global__ void prep_w_kernel(const float* __restrict__ w_enc,
                              const float* __restrict__ w_loc) {
    int tid = threadIdx.x;                 // 0..287
    int r   = tid / 144;
    int k4  = tid - r * 144;
    int a   = blockIdx.x * 2 + r;          // 0..511
    float4 v = make_float4(0.f, 0.f, 0.f, 0.f);
    if (k4 < 128)       v = *(const float4*)(w_enc + (size_t)a * DENC + k4 * 4);
    else if (k4 < 136)  v = *(const float4*)(w_loc + (size_t)a * NFF + (k4 - 128) * 4);
    unsigned short h0, l0, h1, l1, h2, l2, h3, l3;
    cvt_hilo(v.x, h0, l0); cvt_hilo(v.y, h1, l1);
    cvt_hilo(v.z, h2, l2); cvt_hilo(v.w, h3, l3);
    int k = k4 * 4, ch = k >> 5, ci = k & 31;
    char* base = g_ws + (size_t)a * ROWB + ch * 128;
    *(uint2*)(base + ci * 2)      = make_uint2((uint32_t)h0 | ((uint32_t)h1 << 16),
                                               (uint32_t)h2 | ((uint32_t)h3 << 16));
    *(uint2*)(base + 64 + ci * 2) = make_uint2((uint32_t)l0 | ((uint32_t)l1 << 16),
                                               (uint32_t)l2 | ((uint32_t)l3 << 16));
}

// ---------------- fused conv1d + mel projection (branch-dispatched) ----------------
__global__ void convmel_kernel(const float* __restrict__ cum,
                               const float* __restrict__ conv_w,
                               const float* __restrict__ mel,
                               const float* __restrict__ w_in,
                               const float* __restrict__ b_in) {
    int bx = blockIdx.x, tid = threadIdx.x;   // 512 threads
    if (bx < BB) {
        // ---- mel projection: b = bx ----
        __shared__ float ms[DDEC];
        int b = bx;
        int a = tid;
        ms[a]       = mel[b * DDEC + a];
        ms[a + 512] = mel[b * DDEC + a + 512];
        __syncthreads();
        float acc = b_in[a];
        const float4* wr = (const float4*)(w_in + (size_t)a * DDEC);
#pragma unroll 8
        for (int e = 0; e < DDEC / 4; ++e) {
            float4 w = wr[e];
            float4 m = *(const float4*)&ms[e * 4];
            acc += w.x * m.x + w.y * m.y + w.z * m.z + w.w * m.w;
        }
        g_mel[b * AA + a] = acc;
    } else {
        // ---- conv1d(2->32, K=31, SAME): b = bx - BB ----
        __shared__ float ch[2][TT_ + 32];
        __shared__ float cw[NFF][2][KK + 1];
        int b = bx - BB;
        for (int i = tid; i < TT_ + 32; i += 512) {
            float v0 = 0.f, v1 = 0.f;
            int t = i - 15;
            if (t >= 0 && t < TT_) {
                v0 = cum[b * 2 * TT_ + t];
                v1 = cum[b * 2 * TT_ + TT_ + t];
            }
            ch[0][i] = v0; ch[1][i] = v1;
        }
        for (int i = tid; i < NFF * 2 * KK; i += 512) {
            int f = i / (2 * KK);
            int r = i % (2 * KK);
            cw[f][r / KK][r % KK] = conv_w[i];
        }
        __syncthreads();
        for (int idx = tid; idx < TT_ * NFF; idx += 512) {
            int t = idx >> 5;
            int f = idx & 31;
            float acc = 0.f;
#pragma unroll
            for (int k = 0; k < KK; ++k)
                acc += ch[0][t + k] * cw[f][0][k] + ch[1][t + k] * cw[f][1][k];
            g_locfeat[((size_t)b * TT_ + t) * NFF + f] = acc;
        }
    }
}

// ---------------- HMMA energy GEMM: 128m x 128n per CTA, 256 thr, occ 2 --------
__global__ void __launch_bounds__(256, 2)
gemm_energy_kernel(const float* __restrict__ w_energy) {
    extern __shared__ char dsm[];
    __shared__ float mel_s[128];
    __shared__ float weng_s[128];
    __shared__ float red_s[8 * 64];

    uint32_t sdyn = smem_u32(dsm);
    int tid = threadIdx.x, w = tid >> 5, lane = tid & 31;
    int wm = w >> 2, wn = w & 3;           // warp grid 2m x 4n, warp tile 64x32
    int bx   = blockIdx.x;                 // tile*4 + nq (A L2-adjacency)
    int tile = bx >> 2, nq = bx & 3;
    int n0   = nq * 128;
    size_t brow0 = (size_t)tile * 128;
    int b = (int)(brow0 >> 10);

    if (tid < 128) {
        mel_s[tid]  = g_mel[b * AA + n0 + tid];
        weng_s[tid] = w_energy[n0 + tid];
    }

    float acc[4][4][4];
#pragma unroll
    for (int mt = 0; mt < 4; ++mt)
#pragma unroll
        for (int nt = 0; nt < 4; ++nt)
#pragma unroll
            for (int r = 0; r < 4; ++r) acc[mt][nt][r] = 0.f;

    // prologue: stage 0
    {
#pragma unroll
        for (int j = 0; j < 4; ++j) {
            int sg = tid + j * 256;
            int row = sg >> 3, s16 = sg & 7;
            uint32_t sw = SW((uint32_t)(row * 128 + s16 * 16));
            cp16(sdyn + sw,         g_encs + ((brow0 + row) * ROWB) + 0 * 128 + s16 * 16);
            cp16(sdyn + 16384 + sw, g_ws  + ((size_t)(n0 + row) * ROWB) + 0 * 128 + s16 * 16);
        }
        CP_COMMIT();
    }

    for (int kc = 0; kc < NCH; ++kc) {
        if (kc < NCH - 1) {                // issue next stage at top (race-free mod 3)
            uint32_t sb = sdyn + ((kc + 1) % NSTG) * STAGE_BYTES;
#pragma unroll
            for (int j = 0; j < 4; ++j) {
                int sg = tid + j * 256;
                int row = sg >> 3, s16 = sg & 7;
                uint32_t sw = SW((uint32_t)(row * 128 + s16 * 16));
                cp16(sb + sw,         g_encs + ((brow0 + row) * ROWB) + (kc + 1) * 128 + s16 * 16);
                cp16(sb + 16384 + sw, g_ws  + ((size_t)(n0 + row) * ROWB) + (kc + 1) * 128 + s16 * 16);
            }
            CP_COMMIT();
            CP_WAIT1();                    // stage kc arrived (kc+1 may fly)
        } else {
            CP_WAIT0();
        }
        __syncthreads();

        uint32_t sa = sdyn + (kc % NSTG) * STAGE_BYTES;
#pragma unroll
        for (int ks = 0; ks < 2; ++ks) {
            // B: one x4 per nt: hi (lanes 0-15, +0) | lo (lanes 16-31, +64)
            uint32_t bf[4][4];
#pragma unroll
            for (int nt = 0; nt < 4; ++nt) {
                int brow = wn * 32 + nt * 8 + (lane & 7);
                uint32_t off = brow * 128 + ((lane & 16) ? 64u : 0u)
                             + ks * 32 + ((lane >> 3) & 1) * 16;
                ldmx4(bf[nt], sa + 16384 + SW(off));
            }
#pragma unroll
            for (int mt = 0; mt < 4; ++mt) {
                int arow = wm * 64 + mt * 16 + (lane & 15);
                uint32_t abase = arow * 128 + ks * 32 + ((lane >> 4) & 1) * 16;
                uint32_t ah[4], al[4];
                ldmx4(ah, sa + SW(abase));
                ldmx4(al, sa + SW(abase + 64));
#pragma unroll
                for (int nt = 0; nt < 4; ++nt) {
                    mma16816(acc[mt][nt], ah, &bf[nt][0]);
                    mma16816(acc[mt][nt], ah, &bf[nt][2]);
                    mma16816(acc[mt][nt], al, &bf[nt][0]);
                }
            }
        }
    }

    // ---- epilogue: tanh(+mel)*weng, reduce over this CTA's 128 cols ----
#pragma unroll
    for (int mt = 0; mt < 4; ++mt) {
        float s0 = 0.f, s1 = 0.f;
#pragma unroll
        for (int nt = 0; nt < 4; ++nt) {
            int n = wn * 32 + nt * 8 + (lane & 3) * 2;   // local col in [0,128)
            s0 += fast_tanh(acc[mt][nt][0] + mel_s[n]) * weng_s[n]
                + fast_tanh(acc[mt][nt][1] + mel_s[n + 1]) * weng_s[n + 1];
            s1 += fast_tanh(acc[mt][nt][2] + mel_s[n]) * weng_s[n]
                + fast_tanh(acc[mt][nt][3] + mel_s[n + 1]) * weng_s[n + 1];
        }
        s0 += __shfl_xor_sync(0xffffffffu, s0, 1);
        s0 += __shfl_xor_sync(0xffffffffu, s0, 2);
        s1 += __shfl_xor_sync(0xffffffffu, s1, 1);
        s1 += __shfl_xor_sync(0xffffffffu, s1, 2);
        if ((lane & 3) == 0) {
            red_s[w * 64 + mt * 16 + (lane >> 2)]     = s0;
            red_s[w * 64 + mt * 16 + 8 + (lane >> 2)] = s1;
        }
    }
    __syncthreads();
    if (tid < 128) {
        int rwm = tid >> 6, rr = tid & 63;
        float e = 0.f;
#pragma unroll
        for (int wn2 = 0; wn2 < 4; ++wn2)
            e += red_s[(rwm * 4 + wn2) * 64 + rr];
        g_energy4[nq][brow0 + tid] = e;    // disjoint per-nq partials: no atomics
    }
}

// ---------------- softmax (sums 4 partials, applies mask), writes weights ------
__global__ void softmax_kernel(const int* __restrict__ mask, float* __restrict__ out) {
    __shared__ float red[256];
    int b = blockIdx.x, tid = threadIdx.x;
    const int* mk = mask + b * TT_;
    float x[4];
    float m = -INFINITY;
#pragma unroll
    for (int j = 0; j < 4; ++j) {
        int t = b * TT_ + tid + j * 256;
        float e = g_energy4[0][t] + g_energy4[1][t] + g_energy4[2][t] + g_energy4[3][t];
        x[j] = (mk[tid + j * 256] != 0) ? -INFINITY : e;
        m = fmaxf(m, x[j]);
    }
    red[tid] = m; __syncthreads();
    for (int s = 128; s > 0; s >>= 1) {
        if (tid < s) red[tid] = fmaxf(red[tid], red[tid + s]);
        __syncthreads();
    }
    m = red[0]; __syncthreads();
    float sum = 0.f;
#pragma unroll
    for (int j = 0; j < 4; ++j) { x[j] = expf(x[j] - m); sum += x[j]; }
    red[tid] = sum; __syncthreads();
    for (int s = 128; s > 0; s >>= 1) {
        if (tid < s) red[tid] += red[tid + s];
        __syncthreads();
    }
    float inv = 1.0f / red[0];
    float* wout = out + BB * DENC + b * TT_;
#pragma unroll
    for (int j = 0; j < 4; ++j) wout[tid + j * 256] = x[j] * inv;
}

// ---------------- context: split over 8 t-chunks (512 CTAs), then reduce --------
__global__ void ctx_part_kernel(const float* __restrict__ enc,
                                const float* __restrict__ out) {
    __shared__ float ws[128];
    int b = blockIdx.y, ck = blockIdx.x, tid = threadIdx.x;
    int t0 = ck * 128;
    if (tid < 128) ws[tid] = out[BB * DENC + b * TT_ + t0 + tid];
    __syncthreads();
    int e = tid * 2;
    float2 acc = make_float2(0.f, 0.f);
    const float* ep = enc + ((size_t)b * TT_ + t0) * DENC + e;
#pragma unroll 8
    for (int t = 0; t < 128; ++t) {
        float2 v = *(const float2*)(ep + (size_t)t * DENC);
        acc.x += ws[t] * v.x;
        acc.y += ws[t] * v.y;
    }
    *(float2*)&g_ctxp[((size_t)ck * BB + b) * DENC + e] = acc;
}

__global__ void ctx_reduce_kernel(float* __restrict__ out) {
    int b = blockIdx.x, e = threadIdx.x;
    float s = 0.f;
#pragma unroll
    for (int c = 0; c < 8; ++c) s += g_ctxp[((size_t)c * BB + b) * DENC + e];
    out[b * DENC + e] = s;
}

// ---------------- launch ----------------
extern "C" void kernel_launch(void* const* d_in, const int* in_sizes, int n_in,
                              void* d_out, int out_size) {
    const float* mel      = (const float*)d_in[0];
    const float* enc      = (const float*)d_in[1];
    const float* cum      = (const float*)d_in[2];
    const int*   mask     = (const int*)d_in[3];
    const float* w_in     = (const float*)d_in[4];
    const float* b_in     = (const float*)d_in[5];
    const float* w_enc    = (const float*)d_in[6];
    const float* conv_w   = (const float*)d_in[7];
    const float* w_loc    = (const float*)d_in[8];
    const float* w_energy = (const float*)d_in[9];
    float* out = (float*)d_out;

    cudaFuncSetAttribute(gemm_energy_kernel,
                         cudaFuncAttributeMaxDynamicSharedMemorySize, SMEM_DYN);

    convmel_kernel<<<2 * BB, 512>>>(cum, conv_w, mel, w_in, b_in);
    prep_w_kernel<<<AA / 2, 288>>>(w_enc, w_loc);
    prep_enc_kernel<<<BB * TT_ / 2, 288>>>(enc);
    gemm_energy_kernel<<<2048, 256, SMEM_DYN>>>(w_energy);
    softmax_kernel<<<BB, 256>>>(mask, out);
    dim3 gc(8, BB);
    ctx_part_kernel<<<gc, 256>>>(enc, out);
    ctx_reduce_kernel<<<BB, 512>>>(out);
}

// round 17
// speedup vs baseline: 1.1390x; 1.0016x over previous
#include <cuda_runtime.h>
#include <cuda_bf16.h>
#include <stdint.h>
#include <math.h>

#define BB   64
#define TT_  1024
#define DDEC 1024
#define DENC 512
#define AA   512
#define NFF  32
#define KK   31
#define KPAD 576
#define NCH  18                 /* 32-col k-chunks */
#define ROWB 2304               /* bytes per packed row: 18 chunks x 128B (hi64|lo64) */
#define STAGE_BYTES 32768       /* A 16K + B 16K */
#define NSTG 3
#define SMEM_DYN (NSTG * STAGE_BYTES)

#define SW(o) ((o) ^ (((o) >> 3) & 0x70))

// ---------------- device scratch ----------------
__device__ char g_encs[(size_t)BB * TT_ * ROWB];   // packed A: [row][chunk][hi64|lo64]
__device__ char g_ws[(size_t)AA * ROWB];           // packed B: same layout
__device__ float g_locfeat[BB * TT_ * NFF];
__device__ float g_mel[BB * AA];
__device__ float g_energy4[4][BB * TT_];           // per-nq energy partials
__device__ float g_ctxp[16 * BB * DENC];           // 16 ctx partial chunks

// ---------------- helpers ----------------
__device__ __forceinline__ uint32_t smem_u32(const void* p) {
    uint32_t a;
    asm("{ .reg .u64 t; cvta.to.shared.u64 t, %1; cvt.u32.u64 %0, t; }" : "=r"(a) : "l"(p));
    return a;
}
__device__ __forceinline__ void cp16(uint32_t dst, const void* src) {
    asm volatile("cp.async.cg.shared.global [%0], [%1], 16;" :: "r"(dst), "l"(src));
}
#define CP_COMMIT() asm volatile("cp.async.commit_group;" ::: "memory")
#define CP_WAIT1()  asm volatile("cp.async.wait_group 1;" ::: "memory")
#define CP_WAIT0()  asm volatile("cp.async.wait_group 0;" ::: "memory")

__device__ __forceinline__ void ldmx4(uint32_t* r, uint32_t addr) {
    asm volatile("ldmatrix.sync.aligned.m8n8.x4.shared.b16 {%0,%1,%2,%3}, [%4];"
                 : "=r"(r[0]), "=r"(r[1]), "=r"(r[2]), "=r"(r[3]) : "r"(addr));
}
__device__ __forceinline__ void mma16816(float* d, const uint32_t* a, const uint32_t* b) {
    asm volatile("mma.sync.aligned.m16n8k16.row.col.f32.bf16.bf16.f32 "
                 "{%0,%1,%2,%3}, {%4,%5,%6,%7}, {%8,%9}, {%0,%1,%2,%3};"
                 : "+f"(d[0]), "+f"(d[1]), "+f"(d[2]), "+f"(d[3])
                 : "r"(a[0]), "r"(a[1]), "r"(a[2]), "r"(a[3]), "r"(b[0]), "r"(b[1]));
}
__device__ __forceinline__ void cvt_hilo(float x, unsigned short& hi, unsigned short& lo) {
    __nv_bfloat16 h = __float2bfloat16(x);
    float r = x - __bfloat162float(h);
    __nv_bfloat16 l = __float2bfloat16(r);
    hi = *reinterpret_cast<unsigned short*>(&h);
    lo = *reinterpret_cast<unsigned short*>(&l);
}
__device__ __forceinline__ float fast_tanh(float x) {
    x = fminf(fmaxf(x, -15.f), 15.f);
    float t = __expf(2.f * x);
    return __fdividef(t - 1.f, t + 1.f);
}

// ---------------- prep: pack fp32 -> bf16 hi/lo interleaved rows ----------------
// 2 rows per block, 288 threads = 9 full warps (no half-warp waste)
__global__ void prep_enc_kernel(const float* __restrict__ enc) {
    int tid = threadIdx.x;                 // 0..287
    int r   = tid / 144;                   // 0..1
    int k4  = tid - r * 144;               // 0..143
    int row = blockIdx.x * 2 + r;          // 0..65535
    float4 v = make_float4(0.f, 0.f, 0.f, 0.f);
    if (k4 < 128)       v = *(const float4*)(enc + (size_t)row * DENC + k4 * 4);
    else if (k4 < 136)  v = *(const float4*)(g_locfeat + (size_t)row * NFF + (k4 - 128) * 4);
    unsigned short h0, l0, h1, l1, h2, l2, h3, l3;
    cvt_hilo(v.x, h0, l0); cvt_hilo(v.y, h1, l1);
    cvt_hilo(v.z, h2, l2); cvt_hilo(v.w, h3, l3);
    int k = k4 * 4, ch = k >> 5, ci = k & 31;
    char* base = g_encs + (size_t)row * ROWB + ch * 128;
    *(uint2*)(base + ci * 2)      = make_uint2((uint32_t)h0 | ((uint32_t)h1 << 16),
                                               (uint32_t)h2 | ((uint32_t)h3 << 16));
    *(uint2*)(base + 64 + ci * 2) = make_uint2((uint32_t)l0 | ((uint32_t)l1 << 16),
                                               (uint32_t)l2 | ((uint32_t)l3 << 16));
}

__global__ void prep_w_kernel(const float* __restrict__ w_enc,
                              const float* __restrict__ w_loc) {
    int tid = threadIdx.x;                 // 0..287
    int r   = tid / 144;
    int k4  = tid - r * 144;
    int a   = blockIdx.x * 2 + r;          // 0..511
    float4 v = make_float4(0.f, 0.f, 0.f, 0.f);
    if (k4 < 128)       v = *(const float4*)(w_enc + (size_t)a * DENC + k4 * 4);
    else if (k4 < 136)  v = *(const float4*)(w_loc + (size_t)a * NFF + (k4 - 128) * 4);
    unsigned short h0, l0, h1, l1, h2, l2, h3, l3;
    cvt_hilo(v.x, h0, l0); cvt_hilo(v.y, h1, l1);
    cvt_hilo(v.z, h2, l2); cvt_hilo(v.w, h3, l3);
    int k = k4 * 4, ch = k >> 5, ci = k & 31;
    char* base = g_ws + (size_t)a * ROWB + ch * 128;
    *(uint2*)(base + ci * 2)      = make_uint2((uint32_t)h0 | ((uint32_t)h1 << 16),
                                               (uint32_t)h2 | ((uint32_t)h3 << 16));
    *(uint2*)(base + 64 + ci * 2) = make_uint2((uint32_t)l0 | ((uint32_t)l1 << 16),
                                               (uint32_t)l2 | ((uint32_t)l3 << 16));
}

// ---------------- fused conv1d + mel projection (branch-dispatched) ----------------
__global__ void convmel_kernel(const float* __restrict__ cum,
                               const float* __restrict__ conv_w,
                               const float* __restrict__ mel,
                               const float* __restrict__ w_in,
                               const float* __restrict__ b_in) {
    int bx = blockIdx.x, tid = threadIdx.x;   // 512 threads
    if (bx < BB) {
        // ---- mel projection: b = bx ----
        __shared__ float ms[DDEC];
        int b = bx;
        int a = tid;
        ms[a]       = mel[b * DDEC + a];
        ms[a + 512] = mel[b * DDEC + a + 512];
        __syncthreads();
        float acc = b_in[a];
        const float4* wr = (const float4*)(w_in + (size_t)a * DDEC);
#pragma unroll 8
        for (int e = 0; e < DDEC / 4; ++e) {
            float4 w = wr[e];
            float4 m = *(const float4*)&ms[e * 4];
            acc += w.x * m.x + w.y * m.y + w.z * m.z + w.w * m.w;
        }
        g_mel[b * AA + a] = acc;
    } else {
        // ---- conv1d(2->32, K=31, SAME): b = bx - BB ----
        __shared__ float ch[2][TT_ + 32];
        __shared__ float cw[NFF][2][KK + 1];
        int b = bx - BB;
        for (int i = tid; i < TT_ + 32; i += 512) {
            float v0 = 0.f, v1 = 0.f;
            int t = i - 15;
            if (t >= 0 && t < TT_) {
                v0 = cum[b * 2 * TT_ + t];
                v1 = cum[b * 2 * TT_ + TT_ + t];
            }
            ch[0][i] = v0; ch[1][i] = v1;
        }
        for (int i = tid; i < NFF * 2 * KK; i += 512) {
            int f = i / (2 * KK);
            int r = i % (2 * KK);
            cw[f][r / KK][r % KK] = conv_w[i];
        }
        __syncthreads();
        for (int idx = tid; idx < TT_ * NFF; idx += 512) {
            int t = idx >> 5;
            int f = idx & 31;
            float acc = 0.f;
#pragma unroll
            for (int k = 0; k < KK; ++k)
                acc += ch[0][t + k] * cw[f][0][k] + ch[1][t + k] * cw[f][1][k];
            g_locfeat[((size_t)b * TT_ + t) * NFF + f] = acc;
        }
    }
}

// ---------------- HMMA energy GEMM: 128m x 128n per CTA, 256 thr, occ 2 --------
__global__ void __launch_bounds__(256, 2)
gemm_energy_kernel(const float* __restrict__ w_energy) {
    extern __shared__ char dsm[];
    __shared__ float mel_s[128];
    __shared__ float weng_s[128];
    __shared__ float red_s[8 * 64];

    uint32_t sdyn = smem_u32(dsm);
    int tid = threadIdx.x, w = tid >> 5, lane = tid & 31;
    int wm = w >> 2, wn = w & 3;           // warp grid 2m x 4n, warp tile 64x32
    int bx   = blockIdx.x;                 // tile*4 + nq (A L2-adjacency)
    int tile = bx >> 2, nq = bx & 3;
    int n0   = nq * 128;
    size_t brow0 = (size_t)tile * 128;
    int b = (int)(brow0 >> 10);

    if (tid < 128) {
        mel_s[tid]  = g_mel[b * AA + n0 + tid];
        weng_s[tid] = w_energy[n0 + tid];
    }

    float acc[4][4][4];
#pragma unroll
    for (int mt = 0; mt < 4; ++mt)
#pragma unroll
        for (int nt = 0; nt < 4; ++nt)
#pragma unroll
            for (int r = 0; r < 4; ++r) acc[mt][nt][r] = 0.f;

    // prologue: stage 0
    {
#pragma unroll
        for (int j = 0; j < 4; ++j) {
            int sg = tid + j * 256;
            int row = sg >> 3, s16 = sg & 7;
            uint32_t sw = SW((uint32_t)(row * 128 + s16 * 16));
            cp16(sdyn + sw,         g_encs + ((brow0 + row) * ROWB) + 0 * 128 + s16 * 16);
            cp16(sdyn + 16384 + sw, g_ws  + ((size_t)(n0 + row) * ROWB) + 0 * 128 + s16 * 16);
        }
        CP_COMMIT();
    }

    for (int kc = 0; kc < NCH; ++kc) {
        if (kc < NCH - 1) {                // issue next stage at top (race-free mod 3)
            uint32_t sb = sdyn + ((kc + 1) % NSTG) * STAGE_BYTES;
#pragma unroll
            for (int j = 0; j < 4; ++j) {
                int sg = tid + j * 256;
                int row = sg >> 3, s16 = sg & 7;
                uint32_t sw = SW((uint32_t)(row * 128 + s16 * 16));
                cp16(sb + sw,         g_encs + ((brow0 + row) * ROWB) + (kc + 1) * 128 + s16 * 16);
                cp16(sb + 16384 + sw, g_ws  + ((size_t)(n0 + row) * ROWB) + (kc + 1) * 128 + s16 * 16);
            }
            CP_COMMIT();
            CP_WAIT1();                    // stage kc arrived (kc+1 may fly)
        } else {
            CP_WAIT0();
        }
        __syncthreads();

        uint32_t sa = sdyn + (kc % NSTG) * STAGE_BYTES;
#pragma unroll
        for (int ks = 0; ks < 2; ++ks) {
            // B: one x4 per nt: hi (lanes 0-15, +0) | lo (lanes 16-31, +64)
            uint32_t bf[4][4];
#pragma unroll
            for (int nt = 0; nt < 4; ++nt) {
                int brow = wn * 32 + nt * 8 + (lane & 7);
                uint32_t off = brow * 128 + ((lane & 16) ? 64u : 0u)
                             + ks * 32 + ((lane >> 3) & 1) * 16;
                ldmx4(bf[nt], sa + 16384 + SW(off));
            }
#pragma unroll
            for (int mt = 0; mt < 4; ++mt) {
                int arow = wm * 64 + mt * 16 + (lane & 15);
                uint32_t abase = arow * 128 + ks * 32 + ((lane >> 4) & 1) * 16;
                uint32_t ah[4], al[4];
                ldmx4(ah, sa + SW(abase));
                ldmx4(al, sa + SW(abase + 64));
#pragma unroll
                for (int nt = 0; nt < 4; ++nt) {
                    mma16816(acc[mt][nt], ah, &bf[nt][0]);
                    mma16816(acc[mt][nt], ah, &bf[nt][2]);
                    mma16816(acc[mt][nt], al, &bf[nt][0]);
                }
            }
        }
    }

    // ---- epilogue: tanh(+mel)*weng, reduce over this CTA's 128 cols ----
#pragma unroll
    for (int mt = 0; mt < 4; ++mt) {
        float s0 = 0.f, s1 = 0.f;
#pragma unroll
        for (int nt = 0; nt < 4; ++nt) {
            int n = wn * 32 + nt * 8 + (lane & 3) * 2;   // local col in [0,128)
            s0 += fast_tanh(acc[mt][nt][0] + mel_s[n]) * weng_s[n]
                + fast_tanh(acc[mt][nt][1] + mel_s[n + 1]) * weng_s[n + 1];
            s1 += fast_tanh(acc[mt][nt][2] + mel_s[n]) * weng_s[n]
                + fast_tanh(acc[mt][nt][3] + mel_s[n + 1]) * weng_s[n + 1];
        }
        s0 += __shfl_xor_sync(0xffffffffu, s0, 1);
        s0 += __shfl_xor_sync(0xffffffffu, s0, 2);
        s1 += __shfl_xor_sync(0xffffffffu, s1, 1);
        s1 += __shfl_xor_sync(0xffffffffu, s1, 2);
        if ((lane & 3) == 0) {
            red_s[w * 64 + mt * 16 + (lane >> 2)]     = s0;
            red_s[w * 64 + mt * 16 + 8 + (lane >> 2)] = s1;
        }
    }
    __syncthreads();
    if (tid < 128) {
        int rwm = tid >> 6, rr = tid & 63;
        float e = 0.f;
#pragma unroll
        for (int wn2 = 0; wn2 < 4; ++wn2)
            e += red_s[(rwm * 4 + wn2) * 64 + rr];
        g_energy4[nq][brow0 + tid] = e;    // disjoint per-nq partials: no atomics
    }
}

// ---------------- softmax (sums 4 partials, applies mask), writes weights ------
__global__ void softmax_kernel(const int* __restrict__ mask, float* __restrict__ out) {
    __shared__ float red[256];
    int b = blockIdx.x, tid = threadIdx.x;
    const int* mk = mask + b * TT_;
    float x[4];
    float m = -INFINITY;
#pragma unroll
    for (int j = 0; j < 4; ++j) {
        int t = b * TT_ + tid + j * 256;
        float e = g_energy4[0][t] + g_energy4[1][t] + g_energy4[2][t] + g_energy4[3][t];
        x[j] = (mk[tid + j * 256] != 0) ? -INFINITY : e;
        m = fmaxf(m, x[j]);
    }
    red[tid] = m; __syncthreads();
    for (int s = 128; s > 0; s >>= 1) {
        if (tid < s) red[tid] = fmaxf(red[tid], red[tid + s]);
        __syncthreads();
    }
    m = red[0]; __syncthreads();
    float sum = 0.f;
#pragma unroll
    for (int j = 0; j < 4; ++j) { x[j] = expf(x[j] - m); sum += x[j]; }
    red[tid] = sum; __syncthreads();
    for (int s = 128; s > 0; s >>= 1) {
        if (tid < s) red[tid] += red[tid + s];
        __syncthreads();
    }
    float inv = 1.0f / red[0];
    float* wout = out + BB * DENC + b * TT_;
#pragma unroll
    for (int j = 0; j < 4; ++j) wout[tid + j * 256] = x[j] * inv;
}

// ---------------- context: 8 t-chunks x 2 halves, float4 loads, then reduce ------
__global__ void ctx_part_kernel(const float* __restrict__ enc,
                                const float* __restrict__ out) {
    __shared__ float ws[128];
    int b = blockIdx.y, ck = blockIdx.x, tid = threadIdx.x;   // 256 threads
    int t0 = ck * 128;
    if (tid < 128) ws[tid] = out[BB * DENC + b * TT_ + t0 + tid];
    __syncthreads();
    int half = tid >> 7;                   // 0..1: t-subchunk of 64
    int e4   = (tid & 127) * 4;            // 4 cols per thread (float4)
    const float* ep = enc + ((size_t)b * TT_ + t0 + half * 64) * DENC + e4;
    const float* wp = ws + half * 64;
    float4 acc = make_float4(0.f, 0.f, 0.f, 0.f);
#pragma unroll 8
    for (int t = 0; t < 64; ++t) {
        float4 v = *(const float4*)(ep + (size_t)t * DENC);
        float wv = wp[t];
        acc.x += wv * v.x; acc.y += wv * v.y;
        acc.z += wv * v.z; acc.w += wv * v.w;
    }
    *(float4*)&g_ctxp[(((size_t)ck * 2 + half) * BB + b) * DENC + e4] = acc;
}

__global__ void ctx_reduce_kernel(float* __restrict__ out) {
    int b = blockIdx.x, e = threadIdx.x;
    float s = 0.f;
#pragma unroll
    for (int c = 0; c < 16; ++c) s += g_ctxp[((size_t)c * BB + b) * DENC + e];
    out[b * DENC + e] = s;
}

// ---------------- launch ----------------
extern "C" void kernel_launch(void* const* d_in, const int* in_sizes, int n_in,
                              void* d_out, int out_size) {
    const float* mel      = (const float*)d_in[0];
    const float* enc      = (const float*)d_in[1];
    const float* cum      = (const float*)d_in[2];
    const int*   mask     = (const int*)d_in[3];
    const float* w_in     = (const float*)d_in[4];
    const float* b_in     = (const float*)d_in[5];
    const float* w_enc    = (const float*)d_in[6];
    const float* conv_w   = (const float*)d_in[7];
    const float* w_loc    = (const float*)d_in[8];
    const float* w_energy = (const float*)d_in[9];
    float* out = (float*)d_out;

    cudaFuncSetAttribute(gemm_energy_kernel,
                         cudaFuncAttributeMaxDynamicSharedMemorySize, SMEM_DYN);

    convmel_kernel<<<2 * BB, 512>>>(cum, conv_w, mel, w_in, b_in);
    prep_w_kernel<<<AA / 2, 288>>>(w_enc, w_loc);
    prep_enc_kernel<<<BB * TT_ / 2, 288>>>(enc);
    gemm_energy_kernel<<<2048, 256, SMEM_DYN>>>(w_energy);
    softmax_kernel<<<BB, 256>>>(mask, out);
    dim3 gc(8, BB);
    ctx_part_kernel<<<gc, 256>>>(enc, out);
    ctx_reduce_kernel<<<BB, 512>>>(out);
}